// round 10
// baseline (speedup 1.0000x reference)
#include <cuda_runtime.h>
#include <math.h>

// R8 structure (best: 156.1us) with register diet for 8 CTAs/SM:
// 256 threads/CTA, 4 rows staged via cp.async.cg (register-free MLP),
// row-by-row processing with 2 barriers/row; w/b loads moved into the
// per-row epilogue (L1-hot broadcast) so no float4 pair is pinned across
// the kernel; __launch_bounds__(256,8) targets 32 regs -> occ ~100%.
// Streaming __stcs stores.

#define SIZE 1024
#define THREADS 256
#define ROWS 4

__global__ __launch_bounds__(THREADS, 8)
void nan_dense_kernel(const float* __restrict__ X,
                      const float4* __restrict__ w4,
                      const float4* __restrict__ b4,
                      float4* __restrict__ out4)
{
    __shared__ float raw[ROWS * SIZE];      // 16 KB staging
    __shared__ float cmp[SIZE];             // 4 KB compaction buffer
    __shared__ int wtot[8];

    const int t    = threadIdx.x;
    const int lane = t & 31;
    const int wid  = t >> 5;
    const int V    = SIZE / 4;

    const long long r0 = (long long)blockIdx.x * ROWS;
    const float* gsrc = X + r0 * SIZE + (t << 2);
    const unsigned raw_sa = (unsigned)__cvta_generic_to_shared(raw) + (t << 4);

    // Stage all four rows; one commit group per row (FIFO retirement).
#pragma unroll
    for (int r = 0; r < ROWS; ++r) {
        asm volatile(
            "cp.async.cg.shared.global [%0], [%1], 16;\n\t"
            "cp.async.commit_group;\n"
            :: "r"(raw_sa + r * (SIZE * 4)), "l"(gsrc + r * SIZE)
            : "memory");
    }

    const unsigned lt = (1u << lane) - 1u;
    const int base = t << 2;

#pragma unroll
    for (int r = 0; r < ROWS; ++r) {
        // Wait until this row's group has landed (groups retire in order).
        switch (r) {
            case 0: asm volatile("cp.async.wait_group 3;" ::: "memory"); break;
            case 1: asm volatile("cp.async.wait_group 2;" ::: "memory"); break;
            case 2: asm volatile("cp.async.wait_group 1;" ::: "memory"); break;
            default: asm volatile("cp.async.wait_group 0;" ::: "memory"); break;
        }

        // Read back own 16 bytes (written by this thread's own cp.async).
        const float4 cur = reinterpret_cast<const float4*>(raw)[r * V + t];
        float v[4] = {cur.x, cur.y, cur.z, cur.w};

        int pre = 0, wt = 0;
#pragma unroll
        for (int k = 0; k < 4; ++k) {
            const unsigned m = __ballot_sync(0xffffffffu, isfinite(v[k]));
            pre += __popc(m & lt);
            wt  += __popc(m);
        }
        if (lane == 0) wtot[wid] = wt;
        __syncthreads();   // wtot visible; also orders prev row's cmp reads

        int off = 0, total = 0;
#pragma unroll
        for (int i = 0; i < 8; ++i) {
            const int ti = wtot[i];
            total += ti;
            if (i < wid) off += ti;
        }

        int pos = off + pre;
#pragma unroll
        for (int k = 0; k < 4; ++k) {
            if (isfinite(v[k])) cmp[pos++] = v[k];
        }
        __syncthreads();   // scatter complete

        // Epilogue: w/b broadcast loads here (L1-hot; frees 8 pinned regs).
        const float4 wv = __ldg(&w4[t]);
        const float4 bv = __ldg(&b4[t]);
        const float4 sv = reinterpret_cast<const float4*>(cmp)[t];
        float4 o;
        o.x = (base + 0 < total) ? fmaf(sv.x, wv.x, bv.x) : 0.0f;
        o.y = (base + 1 < total) ? fmaf(sv.y, wv.y, bv.y) : 0.0f;
        o.z = (base + 2 < total) ? fmaf(sv.z, wv.z, bv.z) : 0.0f;
        o.w = (base + 3 < total) ? fmaf(sv.w, wv.w, bv.w) : 0.0f;

        __stcs(&out4[(r0 + r) * V + t], o);
    }
}

extern "C" void kernel_launch(void* const* d_in, const int* in_sizes, int n_in,
                              void* d_out, int out_size)
{
    const float* X = (const float*)d_in[0];
    const float* w = (const float*)d_in[1];
    const float* b = (const float*)d_in[2];
    float* out = (float*)d_out;

    const int batch = in_sizes[0] / SIZE;   // 131072 (multiple of 4)
    nan_dense_kernel<<<batch / ROWS, THREADS>>>(
        X,
        reinterpret_cast<const float4*>(w),
        reinterpret_cast<const float4*>(b),
        reinterpret_cast<float4*>(out));
}

// round 11
// speedup vs baseline: 1.0004x; 1.0004x over previous
#include <cuda_runtime.h>
#include <math.h>

// R8 (best, 156.1us) + packed warp-total reads:
// 256 threads/CTA, 4 rows staged via cp.async.cg (register-free MLP, one
// commit group per row, FIFO waits overlap row r compute with rows r+1..
// in flight). Ballot-based stable compaction. Cross-warp reduce now reads
// the 8 warp totals as two int4 LDS.128 broadcasts (was 8 scalar LDS),
// cutting L1 wavefronts on the critical loop. w/b register-resident
// (loaded once per CTA); streaming __stcs stores.

#define SIZE 1024
#define THREADS 256
#define ROWS 4

__global__ __launch_bounds__(THREADS, 6)
void nan_dense_kernel(const float* __restrict__ X,
                      const float4* __restrict__ w4,
                      const float4* __restrict__ b4,
                      float4* __restrict__ out4)
{
    __shared__ float raw[ROWS * SIZE];                   // 16 KB staging
    __shared__ float cmp[SIZE];                          // 4 KB compaction
    __shared__ __align__(16) int wtot[8];

    const int t    = threadIdx.x;
    const int lane = t & 31;
    const int wid  = t >> 5;
    const int V    = SIZE / 4;

    const long long r0 = (long long)blockIdx.x * ROWS;
    const float* gsrc = X + r0 * SIZE + (t << 2);
    const unsigned raw_sa = (unsigned)__cvta_generic_to_shared(raw) + (t << 4);

    // Stage all four rows; one commit group per row (FIFO retirement).
#pragma unroll
    for (int r = 0; r < ROWS; ++r) {
        asm volatile(
            "cp.async.cg.shared.global [%0], [%1], 16;\n\t"
            "cp.async.commit_group;\n"
            :: "r"(raw_sa + r * (SIZE * 4)), "l"(gsrc + r * SIZE)
            : "memory");
    }

    const float4 wv = __ldg(&w4[t]);
    const float4 bv = __ldg(&b4[t]);
    const unsigned lt = (1u << lane) - 1u;
    const int base = t << 2;

#pragma unroll
    for (int r = 0; r < ROWS; ++r) {
        // Wait until this row's group has landed (groups retire in order).
        switch (r) {
            case 0: asm volatile("cp.async.wait_group 3;" ::: "memory"); break;
            case 1: asm volatile("cp.async.wait_group 2;" ::: "memory"); break;
            case 2: asm volatile("cp.async.wait_group 1;" ::: "memory"); break;
            default: asm volatile("cp.async.wait_group 0;" ::: "memory"); break;
        }

        // Read back own 16 bytes (written by this thread's own cp.async).
        const float4 cur = reinterpret_cast<const float4*>(raw)[r * V + t];
        float v[4] = {cur.x, cur.y, cur.z, cur.w};

        int pre = 0, wt = 0;
#pragma unroll
        for (int k = 0; k < 4; ++k) {
            const unsigned m = __ballot_sync(0xffffffffu, isfinite(v[k]));
            pre += __popc(m & lt);
            wt  += __popc(m);
        }
        if (lane == 0) wtot[wid] = wt;
        __syncthreads();   // wtot visible; also orders prev row's cmp reads

        // Packed cross-warp reduce: two LDS.128 broadcasts instead of 8 LDS.
        const int4 p0 = reinterpret_cast<const int4*>(wtot)[0];
        const int4 p1 = reinterpret_cast<const int4*>(wtot)[1];
        const int tt[8] = {p0.x, p0.y, p0.z, p0.w, p1.x, p1.y, p1.z, p1.w};
        int off = 0, total = 0;
#pragma unroll
        for (int i = 0; i < 8; ++i) {
            total += tt[i];
            if (i < wid) off += tt[i];
        }

        int pos = off + pre;
#pragma unroll
        for (int k = 0; k < 4; ++k) {
            if (isfinite(v[k])) cmp[pos++] = v[k];
        }
        __syncthreads();   // scatter complete

        const float4 sv = reinterpret_cast<const float4*>(cmp)[t];
        float4 o;
        o.x = (base + 0 < total) ? fmaf(sv.x, wv.x, bv.x) : 0.0f;
        o.y = (base + 1 < total) ? fmaf(sv.y, wv.y, bv.y) : 0.0f;
        o.z = (base + 2 < total) ? fmaf(sv.z, wv.z, bv.z) : 0.0f;
        o.w = (base + 3 < total) ? fmaf(sv.w, wv.w, bv.w) : 0.0f;

        __stcs(&out4[(r0 + r) * V + t], o);
    }
}

extern "C" void kernel_launch(void* const* d_in, const int* in_sizes, int n_in,
                              void* d_out, int out_size)
{
    const float* X = (const float*)d_in[0];
    const float* w = (const float*)d_in[1];
    const float* b = (const float*)d_in[2];
    float* out = (float*)d_out;

    const int batch = in_sizes[0] / SIZE;   // 131072 (multiple of 4)
    nan_dense_kernel<<<batch / ROWS, THREADS>>>(
        X,
        reinterpret_cast<const float4*>(w),
        reinterpret_cast<const float4*>(b),
        reinterpret_cast<float4*>(out));
}